// round 16
// baseline (speedup 1.0000x reference)
#include <cuda_runtime.h>
#include <cuda_fp16.h>
#include <math.h>

#define NN 100000
#define NE 1600000
#define DIM 128
#define NG  512
#define NC  10
#define BN_EPS 1e-5f
#define NB_SCAN ((NN + 255) / 256)

// ---------------- scratch ---------------------------------------------------------
__device__ __align__(16) __half g_h16[2][(size_t)NN * DIM];  // ping-pong features fp16
__device__ __align__(16) __half g_zl[(size_t)NN * DIM];      // h@Wl fp16 (gathered)
__device__ __align__(16) __half g_zr[(size_t)NN * DIM];      // h@Wr + b fp16 (self)
__device__ __align__(16) __half g_w16[6][DIM * DIM];         // fp16 weights
__device__ float g_deg[NN];
__device__ int   g_degi[NN];
__device__ int   g_rowptr[NN + 1];
__device__ int   g_fill[NN];
__device__ int   g_csr[NE];
__device__ int   g_bsum[NB_SCAN];
__device__ int   g_boff[NB_SCAN];
__device__ float g_gsum[NG * DIM];
__device__ float g_gcnt[NG];
__device__ int   g_is64;

// ---------------- dtype sniffing --------------------------------------------------
__global__ void detect_kernel(const int* ei32) {
    int all_zero = 1;
    for (int i = 0; i < 16; ++i)
        if (ei32[2 * i + 1] != 0) all_zero = 0;
    g_is64 = all_zero;
}

__device__ __forceinline__ int idx_load(const void* p, int i, int is64) {
    if (is64) return (int)((const long long*)p)[i];
    return ((const int*)p)[i];
}

// ---------------- zero helper -----------------------------------------------------
__global__ void zero_stats_kernel() {
    int i = blockIdx.x * blockDim.x + threadIdx.x;
    if (i < NN) g_degi[i] = 0;
    if (i < NG * DIM) g_gsum[i] = 0.f;
    if (i < NG) g_gcnt[i] = 0.f;
}

// ---------------- weight conversion (fp32 -> fp16) --------------------------------
__global__ void convw_kernel(const float* __restrict__ w0, const float* __restrict__ w1,
                             const float* __restrict__ w2, const float* __restrict__ w3,
                             const float* __restrict__ w4, const float* __restrict__ w5) {
    int i = blockIdx.x * blockDim.x + threadIdx.x;
    if (i >= 6 * DIM * DIM) return;
    int m = i / (DIM * DIM), e = i % (DIM * DIM);
    const float* srcs[6] = { w0, w1, w2, w3, w4, w5 };
    g_w16[m][e] = __float2half_rn(srcs[m][e]);
}

// ---------------- BatchNorm (eval) -> fp16 ----------------------------------------
__global__ void bn_kernel(const float* __restrict__ x,
                          const float* __restrict__ gamma, const float* __restrict__ beta,
                          const float* __restrict__ mean,  const float* __restrict__ var) {
    int t = blockIdx.x * blockDim.x + threadIdx.x;
    if (t >= NN * (DIM / 4)) return;
    int c4 = (t & 31) * 4;
    float4 xv = ((const float4*)x)[t];
    float4 m  = *(const float4*)(mean + c4);
    float4 v  = *(const float4*)(var + c4);
    float4 ga = *(const float4*)(gamma + c4);
    float4 be = *(const float4*)(beta + c4);
    float ox = (xv.x - m.x) * rsqrtf(v.x + BN_EPS) * ga.x + be.x;
    float oy = (xv.y - m.y) * rsqrtf(v.y + BN_EPS) * ga.y + be.y;
    float oz = (xv.z - m.z) * rsqrtf(v.z + BN_EPS) * ga.z + be.z;
    float ow = (xv.w - m.w) * rsqrtf(v.w + BN_EPS) * ga.w + be.w;
    __half2 p0 = __floats2half2_rn(ox, oy);
    __half2 p1 = __floats2half2_rn(oz, ow);
    uint2 u; u.x = *(unsigned*)&p0; u.y = *(unsigned*)&p1;
    ((uint2*)g_h16[0])[t] = u;
}

// ---------------- degree + graph counts (merged) ----------------------------------
__global__ void deg_gcnt_kernel(const void* eidx, const void* batch) {
    int e = blockIdx.x * blockDim.x + threadIdx.x;
    int is64 = g_is64;
    if (e < NE) {
        int d = idx_load(eidx, NE + e, is64);
        atomicAdd(&g_degi[d], 1);
    }
    if (e < NN) {
        int b = idx_load(batch, e, is64);
        atomicAdd(&g_gcnt[b], 1.f);
    }
}

// ---------------- CSR build -------------------------------------------------------
__global__ void scan1_kernel() {
    __shared__ int s[256];
    int t = threadIdx.x, b = blockIdx.x;
    int i = b * 256 + t;
    int v = (i < NN) ? g_degi[i] : 0;
    s[t] = v;
    __syncthreads();
#pragma unroll
    for (int off = 1; off < 256; off <<= 1) {
        int x = (t >= off) ? s[t - off] : 0;
        __syncthreads();
        s[t] += x;
        __syncthreads();
    }
    if (i < NN) g_rowptr[i] = s[t] - v;
    if (t == 255) g_bsum[b] = s[255];
}

__global__ void scan2_kernel() {
    __shared__ int s[512];
    int t = threadIdx.x;
    int v = (t < NB_SCAN) ? g_bsum[t] : 0;
    s[t] = v;
    __syncthreads();
#pragma unroll
    for (int off = 1; off < 512; off <<= 1) {
        int x = (t >= off) ? s[t - off] : 0;
        __syncthreads();
        s[t] += x;
        __syncthreads();
    }
    if (t < NB_SCAN) g_boff[t] = s[t] - v;
}

__global__ void scan3_kernel() {
    int i = blockIdx.x * blockDim.x + threadIdx.x;
    if (i >= NN) return;
    int r = g_rowptr[i] + g_boff[i >> 8];
    g_rowptr[i] = r;
    g_fill[i] = r;
    g_deg[i] = 1.f / fmaxf((float)g_degi[i], 1.f);
    if (i == 0) g_rowptr[NN] = NE;
}

__global__ void fill_kernel(const void* eidx) {
    int e = blockIdx.x * blockDim.x + threadIdx.x;
    if (e >= NE) return;
    int is64 = g_is64;
    int s = idx_load(eidx, e, is64);
    int d = idx_load(eidx, NE + e, is64);
    int pos = atomicAdd(&g_fill[d], 1);
    g_csr[pos] = s;
}

// ---------------- tensor-core dual GEMM (R7 two-stage version) --------------------
#define SA_STRIDE 72
#define SB_STRIDE 136
__global__ __launch_bounds__(256, 2)
void gemm_mma_kernel(int layer, const float* __restrict__ bias, int hb_in) {
    __shared__ __half sA[128 * SA_STRIDE];
    __shared__ __half sB[64 * SB_STRIDE];
    const __half* __restrict__ hin = g_h16[hb_in];
    int side = blockIdx.y;
    const __half* __restrict__ W = g_w16[2 * layer + side];

    int t = threadIdx.x;
    int lane = t & 31, warp = t >> 5;
    int wm = warp >> 2, wn = warp & 3;
    int row0 = blockIdx.x * 128;

    unsigned sa_base = (unsigned)__cvta_generic_to_shared(sA);
    unsigned sb_base = (unsigned)__cvta_generic_to_shared(sB);

    float c[4][4][4];
#pragma unroll
    for (int mi = 0; mi < 4; ++mi)
#pragma unroll
        for (int ni = 0; ni < 4; ++ni)
#pragma unroll
            for (int q = 0; q < 4; ++q) c[mi][ni][q] = 0.f;

    for (int k0 = 0; k0 < DIM; k0 += 64) {
#pragma unroll
        for (int p = 0; p < 4; ++p) {
            int idx = t * 4 + p;
            int r = idx >> 3, cch = idx & 7;
            int grow = row0 + r;
            uint4 v = make_uint4(0, 0, 0, 0);
            if (grow < NN)
                v = *(const uint4*)(hin + (size_t)grow * DIM + k0 + cch * 8);
            *(uint4*)&sA[r * SA_STRIDE + cch * 8] = v;
        }
#pragma unroll
        for (int p = 0; p < 4; ++p) {
            int idx = t * 4 + p;
            int r = idx >> 4, cch = idx & 15;
            uint4 v = *(const uint4*)(W + (size_t)(k0 + r) * DIM + cch * 8);
            *(uint4*)&sB[r * SB_STRIDE + cch * 8] = v;
        }
        __syncthreads();

#pragma unroll
        for (int ks = 0; ks < 4; ++ks) {
            int kl = ks * 16;
            unsigned a[4][4];
#pragma unroll
            for (int mi = 0; mi < 4; ++mi) {
                int arow = wm * 64 + mi * 16 + (lane & 15);
                int acol = kl + (lane >> 4) * 8;
                unsigned addr = sa_base + (arow * SA_STRIDE + acol) * 2;
                asm volatile("ldmatrix.sync.aligned.m8n8.x4.shared.b16 {%0,%1,%2,%3}, [%4];"
                             : "=r"(a[mi][0]), "=r"(a[mi][1]), "=r"(a[mi][2]), "=r"(a[mi][3])
                             : "r"(addr));
            }
            unsigned b[4][2];
#pragma unroll
            for (int ni = 0; ni < 4; ++ni) {
                int brow = kl + (lane & 15);
                int bcol = wn * 32 + ni * 8;
                unsigned addr = sb_base + (brow * SB_STRIDE + bcol) * 2;
                asm volatile("ldmatrix.sync.aligned.m8n8.x2.trans.shared.b16 {%0,%1}, [%2];"
                             : "=r"(b[ni][0]), "=r"(b[ni][1]) : "r"(addr));
            }
#pragma unroll
            for (int mi = 0; mi < 4; ++mi)
#pragma unroll
                for (int ni = 0; ni < 4; ++ni)
                    asm volatile(
                        "mma.sync.aligned.m16n8k16.row.col.f32.f16.f16.f32 "
                        "{%0,%1,%2,%3}, {%4,%5,%6,%7}, {%8,%9}, {%0,%1,%2,%3};"
                        : "+f"(c[mi][ni][0]), "+f"(c[mi][ni][1]),
                          "+f"(c[mi][ni][2]), "+f"(c[mi][ni][3])
                        : "r"(a[mi][0]), "r"(a[mi][1]), "r"(a[mi][2]), "r"(a[mi][3]),
                          "r"(b[ni][0]), "r"(b[ni][1]));
        }
        __syncthreads();
    }

    __half* dst = side ? g_zr : g_zl;
#pragma unroll
    for (int mi = 0; mi < 4; ++mi) {
#pragma unroll
        for (int ni = 0; ni < 4; ++ni) {
            int rbase = row0 + wm * 64 + mi * 16 + (lane >> 2);
            int col = wn * 32 + ni * 8 + (lane & 3) * 2;
            float b0 = 0.f, b1 = 0.f;
            if (side) { b0 = bias[col]; b1 = bias[col + 1]; }
            if (rbase < NN) {
                __half2 p = __floats2half2_rn(c[mi][ni][0] + b0, c[mi][ni][1] + b1);
                *(__half2*)(dst + (size_t)rbase * DIM + col) = p;
            }
            if (rbase + 8 < NN) {
                __half2 p = __floats2half2_rn(c[mi][ni][2] + b0, c[mi][ni][3] + b1);
                *(__half2*)(dst + (size_t)(rbase + 8) * DIM + col) = p;
            }
        }
    }
}

// ---------------- gather + mean + residual + relu (MLP-8 unroll) ------------------
__device__ __forceinline__ void acc_h4(float4& a, uint2 v) {
    __half2 h0 = *(__half2*)&v.x, h1 = *(__half2*)&v.y;
    float2 f0 = __half22float2(h0), f1 = __half22float2(h1);
    a.x += f0.x; a.y += f0.y; a.z += f1.x; a.w += f1.y;
}

__global__ void gather_relu_kernel(int hb_out, int last, const void* batch) {
    int w = (blockIdx.x * blockDim.x + threadIdx.x) >> 5;
    if (w >= NN) return;
    int lane = threadIdx.x & 31;
    int start = g_rowptr[w];
    int deg = g_rowptr[w + 1] - start;
    const uint2* __restrict__ zl = (const uint2*)g_zl;
    float4 acc = make_float4(0.f, 0.f, 0.f, 0.f);
    for (int base = 0; base < deg; base += 32) {
        int id = 0;
        if (base + lane < deg) id = g_csr[start + base + lane];
        int n = min(32, deg - base);
        int k = 0;
        for (; k + 8 <= n; k += 8) {          // 8 independent loads in flight
            int s0 = __shfl_sync(0xffffffffu, id, k);
            int s1 = __shfl_sync(0xffffffffu, id, k + 1);
            int s2 = __shfl_sync(0xffffffffu, id, k + 2);
            int s3 = __shfl_sync(0xffffffffu, id, k + 3);
            int s4 = __shfl_sync(0xffffffffu, id, k + 4);
            int s5 = __shfl_sync(0xffffffffu, id, k + 5);
            int s6 = __shfl_sync(0xffffffffu, id, k + 6);
            int s7 = __shfl_sync(0xffffffffu, id, k + 7);
            uint2 v0 = zl[(size_t)s0 * 32 + lane];
            uint2 v1 = zl[(size_t)s1 * 32 + lane];
            uint2 v2 = zl[(size_t)s2 * 32 + lane];
            uint2 v3 = zl[(size_t)s3 * 32 + lane];
            uint2 v4 = zl[(size_t)s4 * 32 + lane];
            uint2 v5 = zl[(size_t)s5 * 32 + lane];
            uint2 v6 = zl[(size_t)s6 * 32 + lane];
            uint2 v7 = zl[(size_t)s7 * 32 + lane];
            acc_h4(acc, v0); acc_h4(acc, v1); acc_h4(acc, v2); acc_h4(acc, v3);
            acc_h4(acc, v4); acc_h4(acc, v5); acc_h4(acc, v6); acc_h4(acc, v7);
        }
        for (; k + 4 <= n; k += 4) {
            int s0 = __shfl_sync(0xffffffffu, id, k);
            int s1 = __shfl_sync(0xffffffffu, id, k + 1);
            int s2 = __shfl_sync(0xffffffffu, id, k + 2);
            int s3 = __shfl_sync(0xffffffffu, id, k + 3);
            uint2 v0 = zl[(size_t)s0 * 32 + lane];
            uint2 v1 = zl[(size_t)s1 * 32 + lane];
            uint2 v2 = zl[(size_t)s2 * 32 + lane];
            uint2 v3 = zl[(size_t)s3 * 32 + lane];
            acc_h4(acc, v0); acc_h4(acc, v1); acc_h4(acc, v2); acc_h4(acc, v3);
        }
        for (; k < n; ++k) {
            int s = __shfl_sync(0xffffffffu, id, k);
            uint2 v = zl[(size_t)s * 32 + lane];
            acc_h4(acc, v);
        }
    }
    float inv = g_deg[w];
    uint2 rv = ((const uint2*)g_zr)[(size_t)w * 32 + lane];
    float4 r;
    {
        __half2 h0 = *(__half2*)&rv.x, h1 = *(__half2*)&rv.y;
        float2 f0 = __half22float2(h0), f1 = __half22float2(h1);
        r.x = f0.x; r.y = f0.y; r.z = f1.x; r.w = f1.y;
    }
    float ox = fmaxf(acc.x * inv + r.x, 0.f);
    float oy = fmaxf(acc.y * inv + r.y, 0.f);
    float oz = fmaxf(acc.z * inv + r.z, 0.f);
    float ow = fmaxf(acc.w * inv + r.w, 0.f);
    if (!last) {
        __half2 p0 = __floats2half2_rn(ox, oy);
        __half2 p1 = __floats2half2_rn(oz, ow);
        uint2 u; u.x = *(unsigned*)&p0; u.y = *(unsigned*)&p1;
        ((uint2*)g_h16[hb_out])[(size_t)w * 32 + lane] = u;
    } else {
        int b = idx_load(batch, w, g_is64);
        float* dst = g_gsum + (size_t)b * DIM + lane * 4;
        asm volatile("red.global.add.v4.f32 [%0], {%1,%2,%3,%4};"
                     :: "l"(dst), "f"(ox), "f"(oy), "f"(oz), "f"(ow) : "memory");
    }
}

// ---------------- head ------------------------------------------------------------
__global__ void head_kernel(const float* __restrict__ Wm1, const float* __restrict__ bm1,
                            const float* __restrict__ Wm2, const float* __restrict__ bm2,
                            float* __restrict__ out) {
    __shared__ float g[DIM], z1[DIM], z2[NC], red2[2];
    int gi = blockIdx.x, t = threadIdx.x;
    float inv_cnt = 1.f / fmaxf(g_gcnt[gi], 1.f);
    g[t] = g_gsum[gi * DIM + t] * inv_cnt;
    __syncthreads();
    float acc = bm1[t];
#pragma unroll 8
    for (int k = 0; k < DIM; ++k) acc += g[k] * Wm1[k * DIM + t];
    z1[t] = acc;
    __syncthreads();
    if (t < NC) {
        float a = bm2[t];
#pragma unroll 8
        for (int k = 0; k < DIM; ++k) a += z1[k] * Wm2[k * NC + t];
        z2[t] = a;
    }
    __syncthreads();
    if (t == 0) {
        float m = -1e30f;
        for (int j = 0; j < NC; ++j) m = fmaxf(m, z2[j]);
        float s = 0.f;
        for (int j = 0; j < NC; ++j) s += expf(z2[j] - m);
        red2[0] = m; red2[1] = logf(s);
    }
    __syncthreads();
    if (t < NC) out[gi * NC + t] = z2[t] - red2[0] - red2[1];
}

// ---------------- launch (fork/join: CSR chain overlaps bn+convw+gemm1) -----------
extern "C" void kernel_launch(void* const* d_in, const int* in_sizes, int n_in,
                              void* d_out, int out_size) {
    const float* x        = (const float*)d_in[0];
    const void*  eidx     = d_in[1];
    const void*  batch    = d_in[2];
    const float* bn_gamma = (const float*)d_in[3];
    const float* bn_beta  = (const float*)d_in[4];
    const float* bn_mean  = (const float*)d_in[5];
    const float* bn_var   = (const float*)d_in[6];
    const float* Wl1 = (const float*)d_in[7];
    const float* Wr1 = (const float*)d_in[8];
    const float* b1  = (const float*)d_in[9];
    const float* Wl2 = (const float*)d_in[10];
    const float* Wr2 = (const float*)d_in[11];
    const float* b2  = (const float*)d_in[12];
    const float* Wl3 = (const float*)d_in[13];
    const float* Wr3 = (const float*)d_in[14];
    const float* b3  = (const float*)d_in[15];
    const float* Wm1 = (const float*)d_in[16];
    const float* bm1 = (const float*)d_in[17];
    const float* Wm2 = (const float*)d_in[18];
    const float* bm2 = (const float*)d_in[19];
    const float* bs[3] = { b1, b2, b3 };
    float* out = (float*)d_out;

    static cudaStream_t s_csr = nullptr;
    static cudaEvent_t ev_fork = nullptr, ev_join = nullptr;
    if (!s_csr) {
        cudaStreamCreateWithFlags(&s_csr, cudaStreamNonBlocking);
        cudaEventCreateWithFlags(&ev_fork, cudaEventDisableTiming);
        cudaEventCreateWithFlags(&ev_join, cudaEventDisableTiming);
    }

    const int T = 256;
    detect_kernel<<<1, 1>>>((const int*)eidx);
    // fork: zero + CSR chain on s_csr (zero_stats only feeds the CSR/pool chain)
    cudaEventRecord(ev_fork, 0);
    cudaStreamWaitEvent(s_csr, ev_fork, 0);
    zero_stats_kernel<<<(NN + T - 1) / T, T, 0, s_csr>>>();
    deg_gcnt_kernel<<<(NE + T - 1) / T, T, 0, s_csr>>>(eidx, batch);
    scan1_kernel<<<NB_SCAN, 256, 0, s_csr>>>();
    scan2_kernel<<<1, 512, 0, s_csr>>>();
    scan3_kernel<<<(NN + T - 1) / T, T, 0, s_csr>>>();
    fill_kernel<<<(NE + T - 1) / T, T, 0, s_csr>>>(eidx);
    cudaEventRecord(ev_join, s_csr);
    // main stream: weights + bn + first GEMM (independent of CSR)
    convw_kernel<<<(6 * DIM * DIM + T - 1) / T, T>>>(Wl1, Wr1, Wl2, Wr2, Wl3, Wr3);
    bn_kernel<<<(NN * 32 + T - 1) / T, T>>>(x, bn_gamma, bn_beta, bn_mean, bn_var);

    int hb = 0;
    dim3 ggrid((NN + 127) / 128, 2);
    for (int l = 0; l < 3; ++l) {
        gemm_mma_kernel<<<ggrid, 256>>>(l, bs[l], hb);
        if (l == 0) cudaStreamWaitEvent(0, ev_join, 0);   // join before first gather
        gather_relu_kernel<<<(NN * 32 + T - 1) / T, T>>>(1 - hb, l == 2 ? 1 : 0, batch);
        hb = 1 - hb;
    }
    head_kernel<<<NG, DIM>>>(Wm1, bm1, Wm2, bm2, out);
}

// round 17
// speedup vs baseline: 1.0889x; 1.0889x over previous
#include <cuda_runtime.h>
#include <cuda_fp16.h>
#include <math.h>

#define NN 100000
#define NE 1600000
#define DIM 128
#define NG  512
#define NC  10
#define BN_EPS 1e-5f
#define NB_SCAN ((NN + 255) / 256)

// ---------------- scratch ---------------------------------------------------------
__device__ __align__(16) __half g_h16[2][(size_t)NN * DIM];  // ping-pong features fp16
__device__ __align__(16) __half g_zl[(size_t)NN * DIM];      // h@Wl fp16 (gathered)
__device__ __align__(16) __half g_zr[(size_t)NN * DIM];      // h@Wr + b fp16 (self)
__device__ __align__(16) __half g_w16[6][DIM * DIM];         // fp16 weights
__device__ float g_deg[NN];
__device__ int   g_degi[NN];
__device__ int   g_rowptr[NN + 1];
__device__ int   g_fill[NN];
__device__ int   g_csr[NE];
__device__ int   g_bsum[NB_SCAN];
__device__ int   g_boff[NB_SCAN];
__device__ float g_gsum[NG * DIM];
__device__ float g_gcnt[NG];
__device__ int   g_is64;

// ---------------- dtype sniffing --------------------------------------------------
__global__ void detect_kernel(const int* ei32) {
    int all_zero = 1;
    for (int i = 0; i < 16; ++i)
        if (ei32[2 * i + 1] != 0) all_zero = 0;
    g_is64 = all_zero;
}

__device__ __forceinline__ int idx_load(const void* p, int i, int is64) {
    if (is64) return (int)((const long long*)p)[i];
    return ((const int*)p)[i];
}

// ---------------- zero helper -----------------------------------------------------
__global__ void zero_stats_kernel() {
    int i = blockIdx.x * blockDim.x + threadIdx.x;
    if (i < NN) g_degi[i] = 0;
    if (i < NG * DIM) g_gsum[i] = 0.f;
    if (i < NG) g_gcnt[i] = 0.f;
}

// ---------------- weight conversion (fp32 -> fp16) --------------------------------
__global__ void convw_kernel(const float* __restrict__ w0, const float* __restrict__ w1,
                             const float* __restrict__ w2, const float* __restrict__ w3,
                             const float* __restrict__ w4, const float* __restrict__ w5) {
    int i = blockIdx.x * blockDim.x + threadIdx.x;
    if (i >= 6 * DIM * DIM) return;
    int m = i / (DIM * DIM), e = i % (DIM * DIM);
    const float* srcs[6] = { w0, w1, w2, w3, w4, w5 };
    g_w16[m][e] = __float2half_rn(srcs[m][e]);
}

// ---------------- BatchNorm (eval) -> fp16 ----------------------------------------
__global__ void bn_kernel(const float* __restrict__ x,
                          const float* __restrict__ gamma, const float* __restrict__ beta,
                          const float* __restrict__ mean,  const float* __restrict__ var) {
    int t = blockIdx.x * blockDim.x + threadIdx.x;
    if (t >= NN * (DIM / 4)) return;
    int c4 = (t & 31) * 4;
    float4 xv = ((const float4*)x)[t];
    float4 m  = *(const float4*)(mean + c4);
    float4 v  = *(const float4*)(var + c4);
    float4 ga = *(const float4*)(gamma + c4);
    float4 be = *(const float4*)(beta + c4);
    float ox = (xv.x - m.x) * rsqrtf(v.x + BN_EPS) * ga.x + be.x;
    float oy = (xv.y - m.y) * rsqrtf(v.y + BN_EPS) * ga.y + be.y;
    float oz = (xv.z - m.z) * rsqrtf(v.z + BN_EPS) * ga.z + be.z;
    float ow = (xv.w - m.w) * rsqrtf(v.w + BN_EPS) * ga.w + be.w;
    __half2 p0 = __floats2half2_rn(ox, oy);
    __half2 p1 = __floats2half2_rn(oz, ow);
    uint2 u; u.x = *(unsigned*)&p0; u.y = *(unsigned*)&p1;
    ((uint2*)g_h16[0])[t] = u;
}

// ---------------- degree + graph counts (merged) ----------------------------------
__global__ void deg_gcnt_kernel(const void* eidx, const void* batch) {
    int e = blockIdx.x * blockDim.x + threadIdx.x;
    int is64 = g_is64;
    if (e < NE) {
        int d = idx_load(eidx, NE + e, is64);
        atomicAdd(&g_degi[d], 1);
    }
    if (e < NN) {
        int b = idx_load(batch, e, is64);
        atomicAdd(&g_gcnt[b], 1.f);
    }
}

// ---------------- CSR build -------------------------------------------------------
__global__ void scan1_kernel() {
    __shared__ int s[256];
    int t = threadIdx.x, b = blockIdx.x;
    int i = b * 256 + t;
    int v = (i < NN) ? g_degi[i] : 0;
    s[t] = v;
    __syncthreads();
#pragma unroll
    for (int off = 1; off < 256; off <<= 1) {
        int x = (t >= off) ? s[t - off] : 0;
        __syncthreads();
        s[t] += x;
        __syncthreads();
    }
    if (i < NN) g_rowptr[i] = s[t] - v;
    if (t == 255) g_bsum[b] = s[255];
}

__global__ void scan2_kernel() {
    __shared__ int s[512];
    int t = threadIdx.x;
    int v = (t < NB_SCAN) ? g_bsum[t] : 0;
    s[t] = v;
    __syncthreads();
#pragma unroll
    for (int off = 1; off < 512; off <<= 1) {
        int x = (t >= off) ? s[t - off] : 0;
        __syncthreads();
        s[t] += x;
        __syncthreads();
    }
    if (t < NB_SCAN) g_boff[t] = s[t] - v;
}

__global__ void scan3_kernel() {
    int i = blockIdx.x * blockDim.x + threadIdx.x;
    if (i >= NN) return;
    int r = g_rowptr[i] + g_boff[i >> 8];
    g_rowptr[i] = r;
    g_fill[i] = r;
    g_deg[i] = 1.f / fmaxf((float)g_degi[i], 1.f);
    if (i == 0) g_rowptr[NN] = NE;
}

__global__ void fill_kernel(const void* eidx) {
    int e = blockIdx.x * blockDim.x + threadIdx.x;
    if (e >= NE) return;
    int is64 = g_is64;
    int s = idx_load(eidx, e, is64);
    int d = idx_load(eidx, NE + e, is64);
    int pos = atomicAdd(&g_fill[d], 1);
    g_csr[pos] = s;
}

// ---------------- tensor-core dual GEMM (R7 two-stage version) --------------------
#define SA_STRIDE 72
#define SB_STRIDE 136
__global__ __launch_bounds__(256, 2)
void gemm_mma_kernel(int layer, const float* __restrict__ bias, int hb_in) {
    __shared__ __half sA[128 * SA_STRIDE];
    __shared__ __half sB[64 * SB_STRIDE];
    const __half* __restrict__ hin = g_h16[hb_in];
    int side = blockIdx.y;
    const __half* __restrict__ W = g_w16[2 * layer + side];

    int t = threadIdx.x;
    int lane = t & 31, warp = t >> 5;
    int wm = warp >> 2, wn = warp & 3;
    int row0 = blockIdx.x * 128;

    unsigned sa_base = (unsigned)__cvta_generic_to_shared(sA);
    unsigned sb_base = (unsigned)__cvta_generic_to_shared(sB);

    float c[4][4][4];
#pragma unroll
    for (int mi = 0; mi < 4; ++mi)
#pragma unroll
        for (int ni = 0; ni < 4; ++ni)
#pragma unroll
            for (int q = 0; q < 4; ++q) c[mi][ni][q] = 0.f;

    for (int k0 = 0; k0 < DIM; k0 += 64) {
#pragma unroll
        for (int p = 0; p < 4; ++p) {
            int idx = t * 4 + p;
            int r = idx >> 3, cch = idx & 7;
            int grow = row0 + r;
            uint4 v = make_uint4(0, 0, 0, 0);
            if (grow < NN)
                v = *(const uint4*)(hin + (size_t)grow * DIM + k0 + cch * 8);
            *(uint4*)&sA[r * SA_STRIDE + cch * 8] = v;
        }
#pragma unroll
        for (int p = 0; p < 4; ++p) {
            int idx = t * 4 + p;
            int r = idx >> 4, cch = idx & 15;
            uint4 v = *(const uint4*)(W + (size_t)(k0 + r) * DIM + cch * 8);
            *(uint4*)&sB[r * SB_STRIDE + cch * 8] = v;
        }
        __syncthreads();

#pragma unroll
        for (int ks = 0; ks < 4; ++ks) {
            int kl = ks * 16;
            unsigned a[4][4];
#pragma unroll
            for (int mi = 0; mi < 4; ++mi) {
                int arow = wm * 64 + mi * 16 + (lane & 15);
                int acol = kl + (lane >> 4) * 8;
                unsigned addr = sa_base + (arow * SA_STRIDE + acol) * 2;
                asm volatile("ldmatrix.sync.aligned.m8n8.x4.shared.b16 {%0,%1,%2,%3}, [%4];"
                             : "=r"(a[mi][0]), "=r"(a[mi][1]), "=r"(a[mi][2]), "=r"(a[mi][3])
                             : "r"(addr));
            }
            unsigned b[4][2];
#pragma unroll
            for (int ni = 0; ni < 4; ++ni) {
                int brow = kl + (lane & 15);
                int bcol = wn * 32 + ni * 8;
                unsigned addr = sb_base + (brow * SB_STRIDE + bcol) * 2;
                asm volatile("ldmatrix.sync.aligned.m8n8.x2.trans.shared.b16 {%0,%1}, [%2];"
                             : "=r"(b[ni][0]), "=r"(b[ni][1]) : "r"(addr));
            }
#pragma unroll
            for (int mi = 0; mi < 4; ++mi)
#pragma unroll
                for (int ni = 0; ni < 4; ++ni)
                    asm volatile(
                        "mma.sync.aligned.m16n8k16.row.col.f32.f16.f16.f32 "
                        "{%0,%1,%2,%3}, {%4,%5,%6,%7}, {%8,%9}, {%0,%1,%2,%3};"
                        : "+f"(c[mi][ni][0]), "+f"(c[mi][ni][1]),
                          "+f"(c[mi][ni][2]), "+f"(c[mi][ni][3])
                        : "r"(a[mi][0]), "r"(a[mi][1]), "r"(a[mi][2]), "r"(a[mi][3]),
                          "r"(b[ni][0]), "r"(b[ni][1]));
        }
        __syncthreads();
    }

    __half* dst = side ? g_zr : g_zl;
#pragma unroll
    for (int mi = 0; mi < 4; ++mi) {
#pragma unroll
        for (int ni = 0; ni < 4; ++ni) {
            int rbase = row0 + wm * 64 + mi * 16 + (lane >> 2);
            int col = wn * 32 + ni * 8 + (lane & 3) * 2;
            float b0 = 0.f, b1 = 0.f;
            if (side) { b0 = bias[col]; b1 = bias[col + 1]; }
            if (rbase < NN) {
                __half2 p = __floats2half2_rn(c[mi][ni][0] + b0, c[mi][ni][1] + b1);
                *(__half2*)(dst + (size_t)rbase * DIM + col) = p;
            }
            if (rbase + 8 < NN) {
                __half2 p = __floats2half2_rn(c[mi][ni][2] + b0, c[mi][ni][3] + b1);
                *(__half2*)(dst + (size_t)(rbase + 8) * DIM + col) = p;
            }
        }
    }
}

// ---------------- gather + mean + residual + relu (R11 MLP-4 + prefetch) ----------
__device__ __forceinline__ void acc_h4(float4& a, uint2 v) {
    __half2 h0 = *(__half2*)&v.x, h1 = *(__half2*)&v.y;
    float2 f0 = __half22float2(h0), f1 = __half22float2(h1);
    a.x += f0.x; a.y += f0.y; a.z += f1.x; a.w += f1.y;
}

__global__ void gather_relu_kernel(int hb_out, int last, const void* batch) {
    int w = (blockIdx.x * blockDim.x + threadIdx.x) >> 5;
    if (w >= NN) return;
    int lane = threadIdx.x & 31;
    int start = g_rowptr[w];
    int deg = g_rowptr[w + 1] - start;
    // prefetch self-path operands so their latency overlaps the gather loop
    float inv = g_deg[w];
    uint2 rv = ((const uint2*)g_zr)[(size_t)w * 32 + lane];
    const uint2* __restrict__ zl = (const uint2*)g_zl;
    float4 acc = make_float4(0.f, 0.f, 0.f, 0.f);
    for (int base = 0; base < deg; base += 32) {
        int id = 0;
        if (base + lane < deg) id = g_csr[start + base + lane];
        int n = min(32, deg - base);
        int k = 0;
        for (; k + 4 <= n; k += 4) {
            int s0 = __shfl_sync(0xffffffffu, id, k);
            int s1 = __shfl_sync(0xffffffffu, id, k + 1);
            int s2 = __shfl_sync(0xffffffffu, id, k + 2);
            int s3 = __shfl_sync(0xffffffffu, id, k + 3);
            uint2 v0 = zl[(size_t)s0 * 32 + lane];
            uint2 v1 = zl[(size_t)s1 * 32 + lane];
            uint2 v2 = zl[(size_t)s2 * 32 + lane];
            uint2 v3 = zl[(size_t)s3 * 32 + lane];
            acc_h4(acc, v0); acc_h4(acc, v1); acc_h4(acc, v2); acc_h4(acc, v3);
        }
        for (; k < n; ++k) {
            int s = __shfl_sync(0xffffffffu, id, k);
            uint2 v = zl[(size_t)s * 32 + lane];
            acc_h4(acc, v);
        }
    }
    float4 r;
    {
        __half2 h0 = *(__half2*)&rv.x, h1 = *(__half2*)&rv.y;
        float2 f0 = __half22float2(h0), f1 = __half22float2(h1);
        r.x = f0.x; r.y = f0.y; r.z = f1.x; r.w = f1.y;
    }
    float ox = fmaxf(acc.x * inv + r.x, 0.f);
    float oy = fmaxf(acc.y * inv + r.y, 0.f);
    float oz = fmaxf(acc.z * inv + r.z, 0.f);
    float ow = fmaxf(acc.w * inv + r.w, 0.f);
    if (!last) {
        __half2 p0 = __floats2half2_rn(ox, oy);
        __half2 p1 = __floats2half2_rn(oz, ow);
        uint2 u; u.x = *(unsigned*)&p0; u.y = *(unsigned*)&p1;
        ((uint2*)g_h16[hb_out])[(size_t)w * 32 + lane] = u;
    } else {
        int b = idx_load(batch, w, g_is64);
        float* dst = g_gsum + (size_t)b * DIM + lane * 4;
        asm volatile("red.global.add.v4.f32 [%0], {%1,%2,%3,%4};"
                     :: "l"(dst), "f"(ox), "f"(oy), "f"(oz), "f"(ow) : "memory");
    }
}

// ---------------- head ------------------------------------------------------------
__global__ void head_kernel(const float* __restrict__ Wm1, const float* __restrict__ bm1,
                            const float* __restrict__ Wm2, const float* __restrict__ bm2,
                            float* __restrict__ out) {
    __shared__ float g[DIM], z1[DIM], z2[NC], red2[2];
    int gi = blockIdx.x, t = threadIdx.x;
    float inv_cnt = 1.f / fmaxf(g_gcnt[gi], 1.f);
    g[t] = g_gsum[gi * DIM + t] * inv_cnt;
    __syncthreads();
    float acc = bm1[t];
#pragma unroll 8
    for (int k = 0; k < DIM; ++k) acc += g[k] * Wm1[k * DIM + t];
    z1[t] = acc;
    __syncthreads();
    if (t < NC) {
        float a = bm2[t];
#pragma unroll 8
        for (int k = 0; k < DIM; ++k) a += z1[k] * Wm2[k * NC + t];
        z2[t] = a;
    }
    __syncthreads();
    if (t == 0) {
        float m = -1e30f;
        for (int j = 0; j < NC; ++j) m = fmaxf(m, z2[j]);
        float s = 0.f;
        for (int j = 0; j < NC; ++j) s += expf(z2[j] - m);
        red2[0] = m; red2[1] = logf(s);
    }
    __syncthreads();
    if (t < NC) out[gi * NC + t] = z2[t] - red2[0] - red2[1];
}

// ---------------- launch (R11 fork/join arrangement) ------------------------------
extern "C" void kernel_launch(void* const* d_in, const int* in_sizes, int n_in,
                              void* d_out, int out_size) {
    const float* x        = (const float*)d_in[0];
    const void*  eidx     = d_in[1];
    const void*  batch    = d_in[2];
    const float* bn_gamma = (const float*)d_in[3];
    const float* bn_beta  = (const float*)d_in[4];
    const float* bn_mean  = (const float*)d_in[5];
    const float* bn_var   = (const float*)d_in[6];
    const float* Wl1 = (const float*)d_in[7];
    const float* Wr1 = (const float*)d_in[8];
    const float* b1  = (const float*)d_in[9];
    const float* Wl2 = (const float*)d_in[10];
    const float* Wr2 = (const float*)d_in[11];
    const float* b2  = (const float*)d_in[12];
    const float* Wl3 = (const float*)d_in[13];
    const float* Wr3 = (const float*)d_in[14];
    const float* b3  = (const float*)d_in[15];
    const float* Wm1 = (const float*)d_in[16];
    const float* bm1 = (const float*)d_in[17];
    const float* Wm2 = (const float*)d_in[18];
    const float* bm2 = (const float*)d_in[19];
    const float* bs[3] = { b1, b2, b3 };
    float* out = (float*)d_out;

    static cudaStream_t s_csr = nullptr;
    static cudaEvent_t ev_fork = nullptr, ev_join = nullptr;
    if (!s_csr) {
        cudaStreamCreateWithFlags(&s_csr, cudaStreamNonBlocking);
        cudaEventCreateWithFlags(&ev_fork, cudaEventDisableTiming);
        cudaEventCreateWithFlags(&ev_join, cudaEventDisableTiming);
    }

    const int T = 256;
    // prologue on the main stream (R11 placement: zero_stats overlaps CSR launch)
    detect_kernel<<<1, 1>>>((const int*)eidx);
    zero_stats_kernel<<<(NN + T - 1) / T, T>>>();
    // fork: CSR chain on s_csr
    cudaEventRecord(ev_fork, 0);
    cudaStreamWaitEvent(s_csr, ev_fork, 0);
    deg_gcnt_kernel<<<(NE + T - 1) / T, T, 0, s_csr>>>(eidx, batch);
    scan1_kernel<<<NB_SCAN, 256, 0, s_csr>>>();
    scan2_kernel<<<1, 512, 0, s_csr>>>();
    scan3_kernel<<<(NN + T - 1) / T, T, 0, s_csr>>>();
    fill_kernel<<<(NE + T - 1) / T, T, 0, s_csr>>>(eidx);
    cudaEventRecord(ev_join, s_csr);
    // main stream: weights + bn + first GEMM (independent of CSR)
    convw_kernel<<<(6 * DIM * DIM + T - 1) / T, T>>>(Wl1, Wr1, Wl2, Wr2, Wl3, Wr3);
    bn_kernel<<<(NN * 32 + T - 1) / T, T>>>(x, bn_gamma, bn_beta, bn_mean, bn_var);

    int hb = 0;
    dim3 ggrid((NN + 127) / 128, 2);
    for (int l = 0; l < 3; ++l) {
        gemm_mma_kernel<<<ggrid, 256>>>(l, bs[l], hb);
        if (l == 0) cudaStreamWaitEvent(0, ev_join, 0);   // join before first gather
        gather_relu_kernel<<<(NN * 32 + T - 1) / T, T>>>(1 - hb, l == 2 ? 1 : 0, batch);
        hb = 1 - hb;
    }
    head_kernel<<<NG, DIM>>>(Wm1, bm1, Wm2, bm2, out);
}